// round 3
// baseline (speedup 1.0000x reference)
#include <cuda_runtime.h>
#include <cstdint>

#define NMAX 50000
#define EMAX 800000
#define NNZMAX (EMAX + NMAX)
#define D 128

// ---------------- scratch (device globals: allocation-free) ----------------
__device__ float g_h[NMAX * D];       // GEMM output per layer
__device__ float g_a[NMAX * D];       // aggregated (post-relu) per layer
__device__ int   g_cnt[NMAX];         // in-degree counts (edges only)
__device__ float g_dis[NMAX];         // deg^{-1/2}
__device__ int   g_rowptr[NMAX + 1];  // CSR row pointers (by dst)
__device__ int   g_cursor[NMAX];      // fill cursors
__device__ int   g_col[NNZMAX];       // CSR cols (src)
__device__ float g_val[NNZMAX];       // CSR vals (norm)

// ---------------- f32x2 helpers (Blackwell FFMA2) ----------------
__device__ __forceinline__ unsigned long long pack2(float a) {
    unsigned long long r;
    unsigned int ai = __float_as_uint(a);
    asm("mov.b64 %0, {%1, %1};" : "=l"(r) : "r"(ai));
    return r;
}
__device__ __forceinline__ unsigned long long fma2(unsigned long long a,
                                                   unsigned long long b,
                                                   unsigned long long c) {
    unsigned long long d_;
    asm("fma.rn.f32x2 %0, %1, %2, %3;" : "=l"(d_) : "l"(a), "l"(b), "l"(c));
    return d_;
}

// ---------------- CSR build ----------------
__global__ void k_zero(int n) {
    int i = blockIdx.x * blockDim.x + threadIdx.x;
    if (i < n) g_cnt[i] = 0;
}

__global__ void k_count(const int* __restrict__ dst, int e) {
    int i = blockIdx.x * blockDim.x + threadIdx.x;
    if (i < e) atomicAdd(&g_cnt[dst[i]], 1);
}

__global__ void k_dis(int n) {
    int i = blockIdx.x * blockDim.x + threadIdx.x;
    if (i < n) g_dis[i] = rsqrtf((float)(g_cnt[i] + 1));  // deg includes self-loop, >= 1
}

// single-block exclusive scan of (cnt[i]+1) -> row_ptr
__global__ void k_scan(int n) {
    __shared__ int s[1024];
    __shared__ int carry;
    int t = threadIdx.x;
    if (t == 0) carry = 0;
    __syncthreads();
    for (int base = 0; base < n; base += 1024) {
        int i = base + t;
        int v = (i < n) ? (g_cnt[i] + 1) : 0;
        s[t] = v;
        __syncthreads();
        #pragma unroll
        for (int off = 1; off < 1024; off <<= 1) {
            int tmp = (t >= off) ? s[t - off] : 0;
            __syncthreads();
            s[t] += tmp;
            __syncthreads();
        }
        if (i < n) g_rowptr[i] = carry + s[t] - v;
        int total = s[1023];
        __syncthreads();
        if (t == 0) carry += total;
        __syncthreads();
    }
    if (t == 0) g_rowptr[n] = carry;
}

__global__ void k_fill_self(int n) {
    int i = blockIdx.x * blockDim.x + threadIdx.x;
    if (i < n) {
        int p = g_rowptr[i];
        g_col[p] = i;
        float d_ = g_dis[i];
        g_val[p] = d_ * d_;
        g_cursor[i] = p + 1;
    }
}

__global__ void k_fill_edges(const int* __restrict__ src,
                             const int* __restrict__ dst, int e) {
    int i = blockIdx.x * blockDim.x + threadIdx.x;
    if (i < e) {
        int s = src[i];
        int d_ = dst[i];
        int p = atomicAdd(&g_cursor[d_], 1);
        g_col[p] = s;
        g_val[p] = g_dis[s] * g_dis[d_];
    }
}

// ---------------- GEMM: out[r][c] = sum_k in[r][k] * W[k][c] ----------------
// 256 threads, 64 rows x 128 cols per block. W fully in SMEM (64KB), A tile 32KB.
// Per thread: 4 rows x 8 cols via FFMA2 (pairs of adjacent columns).
__global__ void k_gemm(const float* __restrict__ in, const float* __restrict__ W,
                       float* __restrict__ out, int nrows) {
    extern __shared__ float sm[];
    float* Ws = sm;            // 128*128
    float* As = sm + D * D;    // 64*128
    int t = threadIdx.x;
    int row0 = blockIdx.x * 64;

    const float4* W4 = (const float4*)W;
    float4* Ws4 = (float4*)Ws;
    #pragma unroll
    for (int i = t; i < D * D / 4; i += 256) Ws4[i] = W4[i];

    float4* As4 = (float4*)As;
    #pragma unroll
    for (int i = t; i < 64 * D / 4; i += 256) {
        int r = i >> 5;           // 32 float4 per row
        int gr = row0 + r;
        float4 v = make_float4(0.f, 0.f, 0.f, 0.f);
        if (gr < nrows) v = ((const float4*)in)[gr * 32 + (i & 31)];
        As4[i] = v;
    }
    __syncthreads();

    int cg = t & 15;   // cols 8*cg .. 8*cg+7
    int rg = t >> 4;   // rows 4*rg .. 4*rg+3
    const float* A0 = As + (4 * rg) * D;

    unsigned long long acc[16];
    #pragma unroll
    for (int i = 0; i < 16; ++i) acc[i] = 0ULL;

    #pragma unroll 2
    for (int k4 = 0; k4 < 32; ++k4) {
        float a0[4], a1[4], a2[4], a3[4];
        *(float4*)a0 = *(const float4*)(A0 + 0 * D + 4 * k4);
        *(float4*)a1 = *(const float4*)(A0 + 1 * D + 4 * k4);
        *(float4*)a2 = *(const float4*)(A0 + 2 * D + 4 * k4);
        *(float4*)a3 = *(const float4*)(A0 + 3 * D + 4 * k4);
        #pragma unroll
        for (int kk = 0; kk < 4; ++kk) {
            int k = 4 * k4 + kk;
            ulonglong2 wA = *(const ulonglong2*)(Ws + k * D + 8 * cg);
            ulonglong2 wB = *(const ulonglong2*)(Ws + k * D + 8 * cg + 4);
            unsigned long long x0 = pack2(a0[kk]);
            unsigned long long x1 = pack2(a1[kk]);
            unsigned long long x2 = pack2(a2[kk]);
            unsigned long long x3 = pack2(a3[kk]);
            acc[0]  = fma2(x0, wA.x, acc[0]);  acc[1]  = fma2(x0, wA.y, acc[1]);
            acc[2]  = fma2(x0, wB.x, acc[2]);  acc[3]  = fma2(x0, wB.y, acc[3]);
            acc[4]  = fma2(x1, wA.x, acc[4]);  acc[5]  = fma2(x1, wA.y, acc[5]);
            acc[6]  = fma2(x1, wB.x, acc[6]);  acc[7]  = fma2(x1, wB.y, acc[7]);
            acc[8]  = fma2(x2, wA.x, acc[8]);  acc[9]  = fma2(x2, wA.y, acc[9]);
            acc[10] = fma2(x2, wB.x, acc[10]); acc[11] = fma2(x2, wB.y, acc[11]);
            acc[12] = fma2(x3, wA.x, acc[12]); acc[13] = fma2(x3, wA.y, acc[13]);
            acc[14] = fma2(x3, wB.x, acc[14]); acc[15] = fma2(x3, wB.y, acc[15]);
        }
    }

    #pragma unroll
    for (int i = 0; i < 4; ++i) {
        int gr = row0 + 4 * rg + i;
        if (gr < nrows) {
            ulonglong2 v0, v1;
            v0.x = acc[4 * i + 0]; v0.y = acc[4 * i + 1];
            v1.x = acc[4 * i + 2]; v1.y = acc[4 * i + 3];
            *(ulonglong2*)(out + gr * D + 8 * cg)     = v0;
            *(ulonglong2*)(out + gr * D + 8 * cg + 4) = v1;
        }
    }
}

// ---------------- SpMM + bias + relu: one warp per output row ----------------
__global__ void k_spmm(const float* __restrict__ h, const float* __restrict__ bias,
                       float* __restrict__ out, int nrows) {
    int w = (blockIdx.x * blockDim.x + threadIdx.x) >> 5;
    int lane = threadIdx.x & 31;
    if (w >= nrows) return;
    int p0 = g_rowptr[w], p1 = g_rowptr[w + 1];
    float4 acc = make_float4(0.f, 0.f, 0.f, 0.f);
    int p = p0;
    for (; p + 2 <= p1; p += 2) {
        int c0 = g_col[p];     float v0 = g_val[p];
        int c1 = g_col[p + 1]; float v1 = g_val[p + 1];
        float4 h0 = *(const float4*)(h + c0 * D + lane * 4);
        float4 h1 = *(const float4*)(h + c1 * D + lane * 4);
        acc.x = fmaf(v0, h0.x, fmaf(v1, h1.x, acc.x));
        acc.y = fmaf(v0, h0.y, fmaf(v1, h1.y, acc.y));
        acc.z = fmaf(v0, h0.z, fmaf(v1, h1.z, acc.z));
        acc.w = fmaf(v0, h0.w, fmaf(v1, h1.w, acc.w));
    }
    if (p < p1) {
        int c0 = g_col[p]; float v0 = g_val[p];
        float4 h0 = *(const float4*)(h + c0 * D + lane * 4);
        acc.x = fmaf(v0, h0.x, acc.x);
        acc.y = fmaf(v0, h0.y, acc.y);
        acc.z = fmaf(v0, h0.z, acc.z);
        acc.w = fmaf(v0, h0.w, acc.w);
    }
    float4 b = *(const float4*)(bias + lane * 4);
    acc.x = fmaxf(acc.x + b.x, 0.f);
    acc.y = fmaxf(acc.y + b.y, 0.f);
    acc.z = fmaxf(acc.z + b.z, 0.f);
    acc.w = fmaxf(acc.w + b.w, 0.f);
    *(float4*)(out + w * D + lane * 4) = acc;
}

// ---------------- pool: batch_vec sorted -> contiguous ranges ----------------
__global__ void k_pool(const float* __restrict__ a, const int* __restrict__ batch,
                       float* __restrict__ out, int n) {
    int g = blockIdx.x, c = threadIdx.x;
    __shared__ int bounds[2];
    if (c < 2) {
        int target = g + c;
        int lo = 0, hi = n;
        while (lo < hi) {
            int mid = (lo + hi) >> 1;
            if (batch[mid] < target) lo = mid + 1; else hi = mid;
        }
        bounds[c] = lo;
    }
    __syncthreads();
    float sum = 0.f;
    for (int r = bounds[0]; r < bounds[1]; ++r) sum += a[r * D + c];
    out[g * D + c] = sum;
}

// ---------------- launch ----------------
extern "C" void kernel_launch(void* const* d_in, const int* in_sizes, int n_in,
                              void* d_out, int out_size) {
    const float* x  = (const float*)d_in[0];
    const float* W1 = (const float*)d_in[1];
    const float* b1 = (const float*)d_in[2];
    const float* W2 = (const float*)d_in[3];
    const float* b2 = (const float*)d_in[4];
    const float* W3 = (const float*)d_in[5];
    const float* b3 = (const float*)d_in[6];
    const int* ei    = (const int*)d_in[7];   // int32 (JAX x64 disabled)
    const int* batch = (const int*)d_in[8];   // int32
    float* out = (float*)d_out;

    int N = in_sizes[0] / D;
    int E = in_sizes[7] / 2;
    int G = out_size / D;

    float *hbuf, *abuf;
    cudaGetSymbolAddress((void**)&hbuf, g_h);
    cudaGetSymbolAddress((void**)&abuf, g_a);

    int smem = (D * D + 64 * D) * (int)sizeof(float);  // 96 KB
    cudaFuncSetAttribute(k_gemm, cudaFuncAttributeMaxDynamicSharedMemorySize, smem);

    int nb = (N + 255) / 256;
    int eb = (E + 255) / 256;

    k_zero<<<nb, 256>>>(N);
    k_count<<<eb, 256>>>(ei + E, E);
    k_dis<<<nb, 256>>>(N);
    k_scan<<<1, 1024>>>(N);
    k_fill_self<<<nb, 256>>>(N);
    k_fill_edges<<<eb, 256>>>(ei, ei + E, E);

    int gb = (N + 63) / 64;
    int sb = (N * 32 + 255) / 256;  // one warp per row

    k_gemm<<<gb, 256, smem>>>(x,    W1, hbuf, N);
    k_spmm<<<sb, 256>>>(hbuf, b1, abuf, N);
    k_gemm<<<gb, 256, smem>>>(abuf, W2, hbuf, N);
    k_spmm<<<sb, 256>>>(hbuf, b2, abuf, N);
    k_gemm<<<gb, 256, smem>>>(abuf, W3, hbuf, N);
    k_spmm<<<sb, 256>>>(hbuf, b3, abuf, N);

    k_pool<<<G, 128>>>(abuf, batch, out, N);
}

// round 4
// speedup vs baseline: 1.2427x; 1.2427x over previous
#include <cuda_runtime.h>
#include <cstdint>

#define NMAX 50000
#define EMAX 800000
#define NNZMAX (EMAX + NMAX)
#define D 128
#define SCAN_B 512
#define NBLK ((NMAX + SCAN_B - 1) / SCAN_B)   // 98

// ---------------- scratch (device globals: allocation-free) ----------------
__device__ float g_h[NMAX * D];       // GEMM output per layer
__device__ float g_a[NMAX * D];       // aggregated (post-relu) per layer
__device__ int   g_cnt[NMAX];         // in-degree counts (edges only)
__device__ float g_dis[NMAX];         // deg^{-1/2}
__device__ int   g_rowptr[NMAX + 1];  // CSR row pointers (by dst)
__device__ int   g_cursor[NMAX];      // fill cursors
__device__ int   g_col[NNZMAX];       // CSR cols (src)
__device__ float g_val[NNZMAX];       // CSR vals (norm)
__device__ int   g_bsum[128];         // per-block sums for scan
__device__ int   g_boff[128];         // per-block offsets

// ---------------- f32x2 helpers (Blackwell FFMA2) ----------------
__device__ __forceinline__ unsigned long long pack2(float a) {
    unsigned long long r;
    unsigned int ai = __float_as_uint(a);
    asm("mov.b64 %0, {%1, %1};" : "=l"(r) : "r"(ai));
    return r;
}
__device__ __forceinline__ unsigned long long fma2(unsigned long long a,
                                                   unsigned long long b,
                                                   unsigned long long c) {
    unsigned long long d_;
    asm("fma.rn.f32x2 %0, %1, %2, %3;" : "=l"(d_) : "l"(a), "l"(b), "l"(c));
    return d_;
}

// ---------------- CSR build ----------------
__global__ void k_zero(int n) {
    int i = blockIdx.x * blockDim.x + threadIdx.x;
    if (i < n) g_cnt[i] = 0;
}

__global__ void k_count(const int* __restrict__ dst, int e) {
    int i = blockIdx.x * blockDim.x + threadIdx.x;
    if (i < e) atomicAdd(&g_cnt[dst[i]], 1);
}

// Pass A: per-block sums of (cnt+1); also compute dis = rsqrt(deg)
__global__ void k_scanA(int n) {
    int t = threadIdx.x;
    int i = blockIdx.x * SCAN_B + t;
    int c = (i < n) ? g_cnt[i] : -1;
    int v = c + 1;                       // 0 for OOB
    if (i < n) g_dis[i] = rsqrtf((float)v);
    int s = v;
    #pragma unroll
    for (int o = 16; o; o >>= 1) s += __shfl_down_sync(0xffffffffu, s, o);
    __shared__ int ws[SCAN_B / 32];
    if ((t & 31) == 0) ws[t >> 5] = s;
    __syncthreads();
    if (t < SCAN_B / 32) {
        int x = ws[t];
        #pragma unroll
        for (int o = SCAN_B / 64; o; o >>= 1) x += __shfl_down_sync(0xffffu, x, o);
        if (t == 0) g_bsum[blockIdx.x] = x;
    }
}

// Pass B: single small block scans the ~98 block sums
__global__ void k_scanB(int nb, int n) {
    __shared__ int s[128];
    int t = threadIdx.x;
    int v = (t < nb) ? g_bsum[t] : 0;
    s[t] = v;
    __syncthreads();
    #pragma unroll
    for (int o = 1; o < 128; o <<= 1) {
        int x = (t >= o) ? s[t - o] : 0;
        __syncthreads();
        s[t] += x;
        __syncthreads();
    }
    g_boff[t] = s[t] - v;
    if (t == 127) g_rowptr[n] = s[127];
}

// Pass C: intra-block exclusive scan -> rowptr; write self-loop entry + cursor
__global__ void k_scanC(int n) {
    int t = threadIdx.x, b = blockIdx.x;
    int i = b * SCAN_B + t;
    int v = (i < n) ? g_cnt[i] + 1 : 0;
    int lane = t & 31, w = t >> 5;
    int x = v;   // inclusive warp scan
    #pragma unroll
    for (int o = 1; o < 32; o <<= 1) {
        int y = __shfl_up_sync(0xffffffffu, x, o);
        if (lane >= o) x += y;
    }
    __shared__ int wsum[SCAN_B / 32];
    if (lane == 31) wsum[w] = x;
    __syncthreads();
    if (t < SCAN_B / 32) {
        int y = wsum[t], z = y;
        #pragma unroll
        for (int o = 1; o < SCAN_B / 32; o <<= 1) {
            int q = __shfl_up_sync(0xffffu, z, o);
            if (t >= o) z += q;
        }
        wsum[t] = z - y;   // exclusive
    }
    __syncthreads();
    int excl = g_boff[b] + wsum[w] + x - v;
    if (i < n) {
        g_rowptr[i] = excl;
        g_col[excl] = i;
        float d_ = g_dis[i];
        g_val[excl] = d_ * d_;
        g_cursor[i] = excl + 1;
    }
}

__global__ void k_fill_edges(const int* __restrict__ src,
                             const int* __restrict__ dst, int e) {
    int i = blockIdx.x * blockDim.x + threadIdx.x;
    if (i < e) {
        int s = src[i];
        int d_ = dst[i];
        int p = atomicAdd(&g_cursor[d_], 1);
        g_col[p] = s;
        g_val[p] = g_dis[s] * g_dis[d_];
    }
}

// ---------------- GEMM: out[r][c] = sum_k in[r][k] * W[k][c] ----------------
__global__ void k_gemm(const float* __restrict__ in, const float* __restrict__ W,
                       float* __restrict__ out, int nrows) {
    extern __shared__ float sm[];
    float* Ws = sm;            // 128*128
    float* As = sm + D * D;    // 64*128
    int t = threadIdx.x;
    int row0 = blockIdx.x * 64;

    const float4* W4 = (const float4*)W;
    float4* Ws4 = (float4*)Ws;
    #pragma unroll
    for (int i = t; i < D * D / 4; i += 256) Ws4[i] = W4[i];

    float4* As4 = (float4*)As;
    #pragma unroll
    for (int i = t; i < 64 * D / 4; i += 256) {
        int r = i >> 5;
        int gr = row0 + r;
        float4 v = make_float4(0.f, 0.f, 0.f, 0.f);
        if (gr < nrows) v = ((const float4*)in)[gr * 32 + (i & 31)];
        As4[i] = v;
    }
    __syncthreads();

    int cg = t & 15;
    int rg = t >> 4;
    const float* A0 = As + (4 * rg) * D;

    unsigned long long acc[16];
    #pragma unroll
    for (int i = 0; i < 16; ++i) acc[i] = 0ULL;

    #pragma unroll 2
    for (int k4 = 0; k4 < 32; ++k4) {
        float a0[4], a1[4], a2[4], a3[4];
        *(float4*)a0 = *(const float4*)(A0 + 0 * D + 4 * k4);
        *(float4*)a1 = *(const float4*)(A0 + 1 * D + 4 * k4);
        *(float4*)a2 = *(const float4*)(A0 + 2 * D + 4 * k4);
        *(float4*)a3 = *(const float4*)(A0 + 3 * D + 4 * k4);
        #pragma unroll
        for (int kk = 0; kk < 4; ++kk) {
            int k = 4 * k4 + kk;
            ulonglong2 wA = *(const ulonglong2*)(Ws + k * D + 8 * cg);
            ulonglong2 wB = *(const ulonglong2*)(Ws + k * D + 8 * cg + 4);
            unsigned long long x0 = pack2(a0[kk]);
            unsigned long long x1 = pack2(a1[kk]);
            unsigned long long x2 = pack2(a2[kk]);
            unsigned long long x3 = pack2(a3[kk]);
            acc[0]  = fma2(x0, wA.x, acc[0]);  acc[1]  = fma2(x0, wA.y, acc[1]);
            acc[2]  = fma2(x0, wB.x, acc[2]);  acc[3]  = fma2(x0, wB.y, acc[3]);
            acc[4]  = fma2(x1, wA.x, acc[4]);  acc[5]  = fma2(x1, wA.y, acc[5]);
            acc[6]  = fma2(x1, wB.x, acc[6]);  acc[7]  = fma2(x1, wB.y, acc[7]);
            acc[8]  = fma2(x2, wA.x, acc[8]);  acc[9]  = fma2(x2, wA.y, acc[9]);
            acc[10] = fma2(x2, wB.x, acc[10]); acc[11] = fma2(x2, wB.y, acc[11]);
            acc[12] = fma2(x3, wA.x, acc[12]); acc[13] = fma2(x3, wA.y, acc[13]);
            acc[14] = fma2(x3, wB.x, acc[14]); acc[15] = fma2(x3, wB.y, acc[15]);
        }
    }

    #pragma unroll
    for (int i = 0; i < 4; ++i) {
        int gr = row0 + 4 * rg + i;
        if (gr < nrows) {
            ulonglong2 v0, v1;
            v0.x = acc[4 * i + 0]; v0.y = acc[4 * i + 1];
            v1.x = acc[4 * i + 2]; v1.y = acc[4 * i + 3];
            *(ulonglong2*)(out + gr * D + 8 * cg)     = v0;
            *(ulonglong2*)(out + gr * D + 8 * cg + 4) = v1;
        }
    }
}

// ---------------- SpMM + bias + relu: one warp per output row, ILP=4 --------
__global__ void k_spmm(const float* __restrict__ h, const float* __restrict__ bias,
                       float* __restrict__ out, int nrows) {
    int w = (blockIdx.x * blockDim.x + threadIdx.x) >> 5;
    int lane = threadIdx.x & 31;
    if (w >= nrows) return;
    int p0 = g_rowptr[w], p1 = g_rowptr[w + 1];
    float4 acc = make_float4(0.f, 0.f, 0.f, 0.f);
    int p = p0;
    for (; p + 4 <= p1; p += 4) {
        int   c0 = g_col[p],     c1 = g_col[p + 1], c2 = g_col[p + 2], c3 = g_col[p + 3];
        float v0 = g_val[p],     v1 = g_val[p + 1], v2 = g_val[p + 2], v3 = g_val[p + 3];
        float4 h0 = *(const float4*)(h + c0 * D + lane * 4);
        float4 h1 = *(const float4*)(h + c1 * D + lane * 4);
        float4 h2 = *(const float4*)(h + c2 * D + lane * 4);
        float4 h3 = *(const float4*)(h + c3 * D + lane * 4);
        acc.x = fmaf(v0, h0.x, fmaf(v1, h1.x, fmaf(v2, h2.x, fmaf(v3, h3.x, acc.x))));
        acc.y = fmaf(v0, h0.y, fmaf(v1, h1.y, fmaf(v2, h2.y, fmaf(v3, h3.y, acc.y))));
        acc.z = fmaf(v0, h0.z, fmaf(v1, h1.z, fmaf(v2, h2.z, fmaf(v3, h3.z, acc.z))));
        acc.w = fmaf(v0, h0.w, fmaf(v1, h1.w, fmaf(v2, h2.w, fmaf(v3, h3.w, acc.w))));
    }
    for (; p < p1; ++p) {
        int c0 = g_col[p]; float v0 = g_val[p];
        float4 h0 = *(const float4*)(h + c0 * D + lane * 4);
        acc.x = fmaf(v0, h0.x, acc.x);
        acc.y = fmaf(v0, h0.y, acc.y);
        acc.z = fmaf(v0, h0.z, acc.z);
        acc.w = fmaf(v0, h0.w, acc.w);
    }
    float4 b = *(const float4*)(bias + lane * 4);
    acc.x = fmaxf(acc.x + b.x, 0.f);
    acc.y = fmaxf(acc.y + b.y, 0.f);
    acc.z = fmaxf(acc.z + b.z, 0.f);
    acc.w = fmaxf(acc.w + b.w, 0.f);
    *(float4*)(out + w * D + lane * 4) = acc;
}

// ---------------- pool: batch_vec sorted -> contiguous ranges ----------------
__global__ void k_pool(const float* __restrict__ a, const int* __restrict__ batch,
                       float* __restrict__ out, int n) {
    int g = blockIdx.x, c = threadIdx.x;
    __shared__ int bounds[2];
    if (c < 2) {
        int target = g + c;
        int lo = 0, hi = n;
        while (lo < hi) {
            int mid = (lo + hi) >> 1;
            if (batch[mid] < target) lo = mid + 1; else hi = mid;
        }
        bounds[c] = lo;
    }
    __syncthreads();
    float sum = 0.f;
    for (int r = bounds[0]; r < bounds[1]; ++r) sum += a[r * D + c];
    out[g * D + c] = sum;
}

// ---------------- launch ----------------
extern "C" void kernel_launch(void* const* d_in, const int* in_sizes, int n_in,
                              void* d_out, int out_size) {
    const float* x  = (const float*)d_in[0];
    const float* W1 = (const float*)d_in[1];
    const float* b1 = (const float*)d_in[2];
    const float* W2 = (const float*)d_in[3];
    const float* b2 = (const float*)d_in[4];
    const float* W3 = (const float*)d_in[5];
    const float* b3 = (const float*)d_in[6];
    const int* ei    = (const int*)d_in[7];
    const int* batch = (const int*)d_in[8];
    float* out = (float*)d_out;

    int N = in_sizes[0] / D;
    int E = in_sizes[7] / 2;
    int G = out_size / D;

    float *hbuf, *abuf;
    cudaGetSymbolAddress((void**)&hbuf, g_h);
    cudaGetSymbolAddress((void**)&abuf, g_a);

    int smem = (D * D + 64 * D) * (int)sizeof(float);  // 96 KB
    cudaFuncSetAttribute(k_gemm, cudaFuncAttributeMaxDynamicSharedMemorySize, smem);

    int nb = (N + 255) / 256;
    int eb = (E + 255) / 256;
    int sbk = (N + SCAN_B - 1) / SCAN_B;   // scan blocks (~98)

    k_zero<<<nb, 256>>>(N);
    k_count<<<eb, 256>>>(ei + E, E);
    k_scanA<<<sbk, SCAN_B>>>(N);
    k_scanB<<<1, 128>>>(sbk, N);
    k_scanC<<<sbk, SCAN_B>>>(N);
    k_fill_edges<<<eb, 256>>>(ei, ei + E, E);

    int gb = (N + 63) / 64;
    int sb = (N * 32 + 255) / 256;

    k_gemm<<<gb, 256, smem>>>(x,    W1, hbuf, N);
    k_spmm<<<sb, 256>>>(hbuf, b1, abuf, N);
    k_gemm<<<gb, 256, smem>>>(abuf, W2, hbuf, N);
    k_spmm<<<sb, 256>>>(hbuf, b2, abuf, N);
    k_gemm<<<gb, 256, smem>>>(abuf, W3, hbuf, N);
    k_spmm<<<sb, 256>>>(hbuf, b3, abuf, N);

    k_pool<<<G, 128>>>(abuf, batch, out, N);
}

// round 5
// speedup vs baseline: 1.3606x; 1.0949x over previous
#include <cuda_runtime.h>
#include <cuda_fp16.h>
#include <cstdint>

#define NMAX 50000
#define EMAX 800000
#define NNZMAX (EMAX + NMAX)
#define D 128
#define SCAN_B 512

// ---------------- scratch (device globals: allocation-free) ----------------
__device__ __half g_h16[NMAX * D];    // GEMM output per layer (fp16)
__device__ float  g_a[NMAX * D];      // aggregated (post-relu) per layer
__device__ int    g_cnt[NMAX];
__device__ float  g_dis[NMAX];
__device__ int    g_rowptr[NMAX + 1];
__device__ int    g_cursor[NMAX];
__device__ int    g_col[NNZMAX];
__device__ float  g_val[NNZMAX];
__device__ int    g_bsum[128];
__device__ int    g_boff[128];

// ---------------- f32x2 helpers (Blackwell FFMA2) ----------------
__device__ __forceinline__ unsigned long long pack2(float a) {
    unsigned long long r;
    unsigned int ai = __float_as_uint(a);
    asm("mov.b64 %0, {%1, %1};" : "=l"(r) : "r"(ai));
    return r;
}
__device__ __forceinline__ unsigned long long fma2(unsigned long long a,
                                                   unsigned long long b,
                                                   unsigned long long c) {
    unsigned long long d_;
    asm("fma.rn.f32x2 %0, %1, %2, %3;" : "=l"(d_) : "l"(a), "l"(b), "l"(c));
    return d_;
}
__device__ __forceinline__ unsigned int f32x2_to_h2(unsigned long long v) {
    unsigned int lo, hi;
    asm("mov.b64 {%0, %1}, %2;" : "=r"(lo), "=r"(hi) : "l"(v));
    __half2 h = __floats2half2_rn(__uint_as_float(lo), __uint_as_float(hi));
    return *reinterpret_cast<unsigned int*>(&h);
}

// ---------------- CSR build ----------------
__global__ void k_zero(int n) {
    int i = blockIdx.x * blockDim.x + threadIdx.x;
    if (i < n) g_cnt[i] = 0;
}

__global__ void k_count(const int* __restrict__ dst, int e) {
    int i = blockIdx.x * blockDim.x + threadIdx.x;
    if (i < e) atomicAdd(&g_cnt[dst[i]], 1);
}

// Pass A: per-block sums of (cnt+1); also dis = rsqrt(deg)
__global__ void k_scanA(int n) {
    int t = threadIdx.x;
    int i = blockIdx.x * SCAN_B + t;
    int c = (i < n) ? g_cnt[i] : -1;
    int v = c + 1;
    if (i < n) g_dis[i] = rsqrtf((float)v);
    int s = v;
    #pragma unroll
    for (int o = 16; o; o >>= 1) s += __shfl_down_sync(0xffffffffu, s, o);
    __shared__ int ws[SCAN_B / 32];
    if ((t & 31) == 0) ws[t >> 5] = s;
    __syncthreads();
    if (t < SCAN_B / 32) {
        int x = ws[t];
        #pragma unroll
        for (int o = SCAN_B / 64; o; o >>= 1) x += __shfl_down_sync(0xffffu, x, o);
        if (t == 0) g_bsum[blockIdx.x] = x;
    }
}

__global__ void k_scanB(int nb, int n) {
    __shared__ int s[128];
    int t = threadIdx.x;
    int v = (t < nb) ? g_bsum[t] : 0;
    s[t] = v;
    __syncthreads();
    #pragma unroll
    for (int o = 1; o < 128; o <<= 1) {
        int x = (t >= o) ? s[t - o] : 0;
        __syncthreads();
        s[t] += x;
        __syncthreads();
    }
    g_boff[t] = s[t] - v;
    if (t == 127) g_rowptr[n] = s[127];
}

// Pass C: intra-block exclusive scan -> rowptr; self-loop entry + cursor
__global__ void k_scanC(int n) {
    int t = threadIdx.x, b = blockIdx.x;
    int i = b * SCAN_B + t;
    int v = (i < n) ? g_cnt[i] + 1 : 0;
    int lane = t & 31, w = t >> 5;
    int x = v;
    #pragma unroll
    for (int o = 1; o < 32; o <<= 1) {
        int y = __shfl_up_sync(0xffffffffu, x, o);
        if (lane >= o) x += y;
    }
    __shared__ int wsum[SCAN_B / 32];
    if (lane == 31) wsum[w] = x;
    __syncthreads();
    if (t < SCAN_B / 32) {
        int y = wsum[t], z = y;
        #pragma unroll
        for (int o = 1; o < SCAN_B / 32; o <<= 1) {
            int q = __shfl_up_sync(0xffffu, z, o);
            if (t >= o) z += q;
        }
        wsum[t] = z - y;
    }
    __syncthreads();
    int excl = g_boff[b] + wsum[w] + x - v;
    if (i < n) {
        g_rowptr[i] = excl;
        g_col[excl] = i;
        float d_ = g_dis[i];
        g_val[excl] = d_ * d_;
        g_cursor[i] = excl + 1;
    }
}

__global__ void k_fill_edges(const int* __restrict__ src,
                             const int* __restrict__ dst, int e) {
    int i = blockIdx.x * blockDim.x + threadIdx.x;
    if (i < e) {
        int s = src[i];
        int d_ = dst[i];
        int p = atomicAdd(&g_cursor[d_], 1);
        g_col[p] = s;
        g_val[p] = g_dis[s] * g_dis[d_];
    }
}

// ---------------- GEMM: out16[r][c] = fp16(sum_k in[r][k] * W[k][c]) --------
__global__ void k_gemm(const float* __restrict__ in, const float* __restrict__ W,
                       __half* __restrict__ out, int nrows) {
    extern __shared__ float sm[];
    float* Ws = sm;            // 128*128
    float* As = sm + D * D;    // 64*128
    int t = threadIdx.x;
    int row0 = blockIdx.x * 64;

    const float4* W4 = (const float4*)W;
    float4* Ws4 = (float4*)Ws;
    #pragma unroll
    for (int i = t; i < D * D / 4; i += 256) Ws4[i] = W4[i];

    float4* As4 = (float4*)As;
    #pragma unroll
    for (int i = t; i < 64 * D / 4; i += 256) {
        int r = i >> 5;
        int gr = row0 + r;
        float4 v = make_float4(0.f, 0.f, 0.f, 0.f);
        if (gr < nrows) v = ((const float4*)in)[gr * 32 + (i & 31)];
        As4[i] = v;
    }
    __syncthreads();

    int cg = t & 15;
    int rg = t >> 4;
    const float* A0 = As + (4 * rg) * D;

    unsigned long long acc[16];
    #pragma unroll
    for (int i = 0; i < 16; ++i) acc[i] = 0ULL;

    #pragma unroll 2
    for (int k4 = 0; k4 < 32; ++k4) {
        float a0[4], a1[4], a2[4], a3[4];
        *(float4*)a0 = *(const float4*)(A0 + 0 * D + 4 * k4);
        *(float4*)a1 = *(const float4*)(A0 + 1 * D + 4 * k4);
        *(float4*)a2 = *(const float4*)(A0 + 2 * D + 4 * k4);
        *(float4*)a3 = *(const float4*)(A0 + 3 * D + 4 * k4);
        #pragma unroll
        for (int kk = 0; kk < 4; ++kk) {
            int k = 4 * k4 + kk;
            ulonglong2 wA = *(const ulonglong2*)(Ws + k * D + 8 * cg);
            ulonglong2 wB = *(const ulonglong2*)(Ws + k * D + 8 * cg + 4);
            unsigned long long x0 = pack2(a0[kk]);
            unsigned long long x1 = pack2(a1[kk]);
            unsigned long long x2 = pack2(a2[kk]);
            unsigned long long x3 = pack2(a3[kk]);
            acc[0]  = fma2(x0, wA.x, acc[0]);  acc[1]  = fma2(x0, wA.y, acc[1]);
            acc[2]  = fma2(x0, wB.x, acc[2]);  acc[3]  = fma2(x0, wB.y, acc[3]);
            acc[4]  = fma2(x1, wA.x, acc[4]);  acc[5]  = fma2(x1, wA.y, acc[5]);
            acc[6]  = fma2(x1, wB.x, acc[6]);  acc[7]  = fma2(x1, wB.y, acc[7]);
            acc[8]  = fma2(x2, wA.x, acc[8]);  acc[9]  = fma2(x2, wA.y, acc[9]);
            acc[10] = fma2(x2, wB.x, acc[10]); acc[11] = fma2(x2, wB.y, acc[11]);
            acc[12] = fma2(x3, wA.x, acc[12]); acc[13] = fma2(x3, wA.y, acc[13]);
            acc[14] = fma2(x3, wB.x, acc[14]); acc[15] = fma2(x3, wB.y, acc[15]);
        }
    }

    #pragma unroll
    for (int i = 0; i < 4; ++i) {
        int gr = row0 + 4 * rg + i;
        if (gr < nrows) {
            uint4 v;
            v.x = f32x2_to_h2(acc[4 * i + 0]);
            v.y = f32x2_to_h2(acc[4 * i + 1]);
            v.z = f32x2_to_h2(acc[4 * i + 2]);
            v.w = f32x2_to_h2(acc[4 * i + 3]);
            *(uint4*)(out + gr * D + 8 * cg) = v;   // 16B: 8 fp16 cols
        }
    }
}

// ---------------- SpMM + bias + relu: one warp/row, fp16 gather, ILP=4 ------
__device__ __forceinline__ void acc_row(const __half* __restrict__ h, int c, int lane,
                                        float v, float4& acc) {
    uint2 raw = *(const uint2*)(h + c * D + lane * 4);
    __half2 h0 = *reinterpret_cast<__half2*>(&raw.x);
    __half2 h1 = *reinterpret_cast<__half2*>(&raw.y);
    float2 f0 = __half22float2(h0);
    float2 f1 = __half22float2(h1);
    acc.x = fmaf(v, f0.x, acc.x);
    acc.y = fmaf(v, f0.y, acc.y);
    acc.z = fmaf(v, f1.x, acc.z);
    acc.w = fmaf(v, f1.y, acc.w);
}

__global__ void k_spmm(const __half* __restrict__ h, const float* __restrict__ bias,
                       float* __restrict__ out, int nrows) {
    int w = (blockIdx.x * blockDim.x + threadIdx.x) >> 5;
    int lane = threadIdx.x & 31;
    if (w >= nrows) return;
    int p0 = g_rowptr[w], p1 = g_rowptr[w + 1];
    float4 acc = make_float4(0.f, 0.f, 0.f, 0.f);
    int p = p0;
    for (; p + 4 <= p1; p += 4) {
        int   c0 = g_col[p],     c1 = g_col[p + 1], c2 = g_col[p + 2], c3 = g_col[p + 3];
        float v0 = g_val[p],     v1 = g_val[p + 1], v2 = g_val[p + 2], v3 = g_val[p + 3];
        uint2 r0 = *(const uint2*)(h + c0 * D + lane * 4);
        uint2 r1 = *(const uint2*)(h + c1 * D + lane * 4);
        uint2 r2 = *(const uint2*)(h + c2 * D + lane * 4);
        uint2 r3 = *(const uint2*)(h + c3 * D + lane * 4);
        float2 a0 = __half22float2(*reinterpret_cast<__half2*>(&r0.x));
        float2 b0 = __half22float2(*reinterpret_cast<__half2*>(&r0.y));
        float2 a1 = __half22float2(*reinterpret_cast<__half2*>(&r1.x));
        float2 b1 = __half22float2(*reinterpret_cast<__half2*>(&r1.y));
        float2 a2 = __half22float2(*reinterpret_cast<__half2*>(&r2.x));
        float2 b2 = __half22float2(*reinterpret_cast<__half2*>(&r2.y));
        float2 a3 = __half22float2(*reinterpret_cast<__half2*>(&r3.x));
        float2 b3 = __half22float2(*reinterpret_cast<__half2*>(&r3.y));
        acc.x = fmaf(v0, a0.x, fmaf(v1, a1.x, fmaf(v2, a2.x, fmaf(v3, a3.x, acc.x))));
        acc.y = fmaf(v0, a0.y, fmaf(v1, a1.y, fmaf(v2, a2.y, fmaf(v3, a3.y, acc.y))));
        acc.z = fmaf(v0, b0.x, fmaf(v1, b1.x, fmaf(v2, b2.x, fmaf(v3, b3.x, acc.z))));
        acc.w = fmaf(v0, b0.y, fmaf(v1, b1.y, fmaf(v2, b2.y, fmaf(v3, b3.y, acc.w))));
    }
    for (; p < p1; ++p) {
        acc_row(h, g_col[p], lane, g_val[p], acc);
    }
    float4 b = *(const float4*)(bias + lane * 4);
    acc.x = fmaxf(acc.x + b.x, 0.f);
    acc.y = fmaxf(acc.y + b.y, 0.f);
    acc.z = fmaxf(acc.z + b.z, 0.f);
    acc.w = fmaxf(acc.w + b.w, 0.f);
    *(float4*)(out + w * D + lane * 4) = acc;
}

// ---------------- pool: batch_vec sorted -> contiguous ranges ----------------
__global__ void k_pool(const float* __restrict__ a, const int* __restrict__ batch,
                       float* __restrict__ out, int n) {
    int g = blockIdx.x, c = threadIdx.x;
    __shared__ int bounds[2];
    if (c < 2) {
        int target = g + c;
        int lo = 0, hi = n;
        while (lo < hi) {
            int mid = (lo + hi) >> 1;
            if (batch[mid] < target) lo = mid + 1; else hi = mid;
        }
        bounds[c] = lo;
    }
    __syncthreads();
    float sum = 0.f;
    for (int r = bounds[0]; r < bounds[1]; ++r) sum += a[r * D + c];
    out[g * D + c] = sum;
}

// ---------------- launch ----------------
extern "C" void kernel_launch(void* const* d_in, const int* in_sizes, int n_in,
                              void* d_out, int out_size) {
    const float* x  = (const float*)d_in[0];
    const float* W1 = (const float*)d_in[1];
    const float* b1 = (const float*)d_in[2];
    const float* W2 = (const float*)d_in[3];
    const float* b2 = (const float*)d_in[4];
    const float* W3 = (const float*)d_in[5];
    const float* b3 = (const float*)d_in[6];
    const int* ei    = (const int*)d_in[7];
    const int* batch = (const int*)d_in[8];
    float* out = (float*)d_out;

    int N = in_sizes[0] / D;
    int E = in_sizes[7] / 2;
    int G = out_size / D;

    __half* hbuf;
    float* abuf;
    cudaGetSymbolAddress((void**)&hbuf, g_h16);
    cudaGetSymbolAddress((void**)&abuf, g_a);

    int smem = (D * D + 64 * D) * (int)sizeof(float);  // 96 KB
    cudaFuncSetAttribute(k_gemm, cudaFuncAttributeMaxDynamicSharedMemorySize, smem);

    int nb = (N + 255) / 256;
    int eb = (E + 255) / 256;
    int sbk = (N + SCAN_B - 1) / SCAN_B;

    k_zero<<<nb, 256>>>(N);
    k_count<<<eb, 256>>>(ei + E, E);
    k_scanA<<<sbk, SCAN_B>>>(N);
    k_scanB<<<1, 128>>>(sbk, N);
    k_scanC<<<sbk, SCAN_B>>>(N);
    k_fill_edges<<<eb, 256>>>(ei, ei + E, E);

    int gb = (N + 63) / 64;
    int sb = (N * 32 + 255) / 256;

    k_gemm<<<gb, 256, smem>>>(x,    W1, hbuf, N);
    k_spmm<<<sb, 256>>>(hbuf, b1, abuf, N);
    k_gemm<<<gb, 256, smem>>>(abuf, W2, hbuf, N);
    k_spmm<<<sb, 256>>>(hbuf, b2, abuf, N);
    k_gemm<<<gb, 256, smem>>>(abuf, W3, hbuf, N);
    k_spmm<<<sb, 256>>>(hbuf, b3, abuf, N);

    k_pool<<<G, 128>>>(abuf, batch, out, N);
}

// round 6
// speedup vs baseline: 2.5675x; 1.8871x over previous
#include <cuda_runtime.h>
#include <cuda_fp16.h>
#include <cstdint>

#define NMAX 50000
#define EMAX 800000
#define NNZMAX (EMAX + NMAX)
#define D 128
#define SCAN_B 512
#define APITCH 136   // padded row pitch in halves (272B): conflict-free ldmatrix

// ---------------- scratch (device globals: allocation-free) ----------------
__device__ __half g_x16[NMAX * D];    // input x in fp16
__device__ __half g_h16[NMAX * D];    // GEMM output per layer (fp16)
__device__ __half g_a16[NMAX * D];    // aggregated (post-relu) per layer (fp16)
__device__ int    g_cnt[NMAX];
__device__ float  g_dis[NMAX];
__device__ int    g_rowptr[NMAX + 1];
__device__ int    g_cursor[NMAX];
__device__ int    g_col[NNZMAX];
__device__ float  g_val[NNZMAX];
__device__ int    g_bsum[128];
__device__ int    g_boff[128];

// ---------------- mma helpers ----------------
__device__ __forceinline__ uint32_t smem_u32(const void* p) {
    return (uint32_t)__cvta_generic_to_shared(p);
}
__device__ __forceinline__ void ldmA(uint32_t* r, uint32_t addr) {
    asm volatile("ldmatrix.sync.aligned.m8n8.x4.shared.b16 {%0,%1,%2,%3}, [%4];"
        : "=r"(r[0]), "=r"(r[1]), "=r"(r[2]), "=r"(r[3]) : "r"(addr));
}
__device__ __forceinline__ void ldmB(uint32_t* r, uint32_t addr) {
    asm volatile("ldmatrix.sync.aligned.m8n8.x2.trans.shared.b16 {%0,%1}, [%2];"
        : "=r"(r[0]), "=r"(r[1]) : "r"(addr));
}
__device__ __forceinline__ void mma16816(float* c, const uint32_t* a, const uint32_t* b) {
    asm volatile("mma.sync.aligned.m16n8k16.row.col.f32.f16.f16.f32 "
        "{%0,%1,%2,%3}, {%4,%5,%6,%7}, {%8,%9}, {%0,%1,%2,%3};"
        : "+f"(c[0]), "+f"(c[1]), "+f"(c[2]), "+f"(c[3])
        : "r"(a[0]), "r"(a[1]), "r"(a[2]), "r"(a[3]), "r"(b[0]), "r"(b[1]));
}

// ---------------- CSR build ----------------
__global__ void k_zero(int n) {
    int i = blockIdx.x * blockDim.x + threadIdx.x;
    if (i < n) g_cnt[i] = 0;
}

__global__ void k_count(const int* __restrict__ dst, int e) {
    int i = blockIdx.x * blockDim.x + threadIdx.x;
    if (i < e) atomicAdd(&g_cnt[dst[i]], 1);
}

__global__ void k_scanA(int n) {
    int t = threadIdx.x;
    int i = blockIdx.x * SCAN_B + t;
    int c = (i < n) ? g_cnt[i] : -1;
    int v = c + 1;
    if (i < n) g_dis[i] = rsqrtf((float)v);
    int s = v;
    #pragma unroll
    for (int o = 16; o; o >>= 1) s += __shfl_down_sync(0xffffffffu, s, o);
    __shared__ int ws[SCAN_B / 32];
    if ((t & 31) == 0) ws[t >> 5] = s;
    __syncthreads();
    if (t < SCAN_B / 32) {
        int x = ws[t];
        #pragma unroll
        for (int o = SCAN_B / 64; o; o >>= 1) x += __shfl_down_sync(0xffffu, x, o);
        if (t == 0) g_bsum[blockIdx.x] = x;
    }
}

__global__ void k_scanB(int nb, int n) {
    __shared__ int s[128];
    int t = threadIdx.x;
    int v = (t < nb) ? g_bsum[t] : 0;
    s[t] = v;
    __syncthreads();
    #pragma unroll
    for (int o = 1; o < 128; o <<= 1) {
        int x = (t >= o) ? s[t - o] : 0;
        __syncthreads();
        s[t] += x;
        __syncthreads();
    }
    g_boff[t] = s[t] - v;
    if (t == 127) g_rowptr[n] = s[127];
}

__global__ void k_scanC(int n) {
    int t = threadIdx.x, b = blockIdx.x;
    int i = b * SCAN_B + t;
    int v = (i < n) ? g_cnt[i] + 1 : 0;
    int lane = t & 31, w = t >> 5;
    int x = v;
    #pragma unroll
    for (int o = 1; o < 32; o <<= 1) {
        int y = __shfl_up_sync(0xffffffffu, x, o);
        if (lane >= o) x += y;
    }
    __shared__ int wsum[SCAN_B / 32];
    if (lane == 31) wsum[w] = x;
    __syncthreads();
    if (t < SCAN_B / 32) {
        int y = wsum[t], z = y;
        #pragma unroll
        for (int o = 1; o < SCAN_B / 32; o <<= 1) {
            int q = __shfl_up_sync(0xffffu, z, o);
            if (t >= o) z += q;
        }
        wsum[t] = z - y;
    }
    __syncthreads();
    int excl = g_boff[b] + wsum[w] + x - v;
    if (i < n) {
        g_rowptr[i] = excl;
        g_col[excl] = i;
        float d_ = g_dis[i];
        g_val[excl] = d_ * d_;
        g_cursor[i] = excl + 1;
    }
}

__global__ void k_fill_edges(const int* __restrict__ src,
                             const int* __restrict__ dst, int e) {
    int i = blockIdx.x * blockDim.x + threadIdx.x;
    if (i < e) {
        int s = src[i];
        int d_ = dst[i];
        int p = atomicAdd(&g_cursor[d_], 1);
        g_col[p] = s;
        g_val[p] = g_dis[s] * g_dis[d_];
    }
}

// ---------------- x fp32 -> fp16 ----------------
__global__ void k_cvt(const float* __restrict__ x, __half* __restrict__ o, int n4) {
    int i = blockIdx.x * blockDim.x + threadIdx.x;
    if (i < n4) {
        float4 v = ((const float4*)x)[i];
        uint2 r;
        __half2 h0 = __floats2half2_rn(v.x, v.y);
        __half2 h1 = __floats2half2_rn(v.z, v.w);
        r.x = *reinterpret_cast<uint32_t*>(&h0);
        r.y = *reinterpret_cast<uint32_t*>(&h1);
        ((uint2*)o)[i] = r;
    }
}

// ---------------- GEMM via HMMA: out16 = in16 @ W (W fp32 in gmem) ----------
// block = 256 thr = 8 warps (4m x 2n); tile 128(m) x 128(n) x 128(k)
__global__ void k_gemm_mma(const __half* __restrict__ in, const float* __restrict__ Wf,
                           __half* __restrict__ out, int nrows) {
    extern __shared__ __half sm16[];
    __half* As = sm16;                  // 128 x APITCH
    __half* Ws = sm16 + 128 * APITCH;   // 128 x APITCH (row-major W[k][n])
    int t = threadIdx.x;
    int row0 = blockIdx.x * 128;

    // stage W: fp32 -> fp16, padded rows
    #pragma unroll
    for (int i = t; i < 128 * 32; i += 256) {       // 32 float4 per row of 128
        int r = i >> 5, c4 = i & 31;
        float4 v = ((const float4*)Wf)[r * 32 + c4];
        __half2 h0 = __floats2half2_rn(v.x, v.y);
        __half2 h1 = __floats2half2_rn(v.z, v.w);
        *(__half2*)(Ws + r * APITCH + c4 * 4)     = h0;
        *(__half2*)(Ws + r * APITCH + c4 * 4 + 2) = h1;
    }
    // stage A: fp16 rows (16 uint4 per row)
    #pragma unroll
    for (int i = t; i < 128 * 16; i += 256) {
        int r = i >> 4, c8 = i & 15;
        int gr = row0 + r;
        uint4 v = make_uint4(0u, 0u, 0u, 0u);
        if (gr < nrows) v = ((const uint4*)(in + gr * D))[c8];
        *(uint4*)(As + r * APITCH + c8 * 8) = v;
    }
    __syncthreads();

    int wid = t >> 5, lane = t & 31;
    int wm = wid & 3, wn = wid >> 1 & 1;   // 4 m-warps x 2 n-warps
    wn = wid >> 2;                          // correct: wid 0-3 -> wn 0, 4-7 -> wn 1

    float c[2][8][4];
    #pragma unroll
    for (int mi = 0; mi < 2; ++mi)
        #pragma unroll
        for (int ni = 0; ni < 8; ++ni)
            #pragma unroll
            for (int j = 0; j < 4; ++j) c[mi][ni][j] = 0.f;

    int arow = wm * 32 + (lane & 15);
    int acol_sel = (lane >> 4) * 8;
    int brow = lane & 15;
    int bcol0 = wn * 64;

    #pragma unroll
    for (int k0 = 0; k0 < 128; k0 += 16) {
        uint32_t a[2][4];
        #pragma unroll
        for (int mi = 0; mi < 2; ++mi) {
            uint32_t addr = smem_u32(As + (arow + mi * 16) * APITCH + k0 + acol_sel);
            ldmA(a[mi], addr);
        }
        uint32_t b[8][2];
        #pragma unroll
        for (int ni = 0; ni < 8; ++ni) {
            uint32_t addr = smem_u32(Ws + (k0 + brow) * APITCH + bcol0 + ni * 8);
            ldmB(b[ni], addr);
        }
        #pragma unroll
        for (int mi = 0; mi < 2; ++mi)
            #pragma unroll
            for (int ni = 0; ni < 8; ++ni)
                mma16816(c[mi][ni], a[mi], b[ni]);
    }

    // epilogue: fp32 -> fp16 stores
    int r = lane >> 2, cc = (lane & 3) * 2;
    #pragma unroll
    for (int mi = 0; mi < 2; ++mi) {
        int gr0 = row0 + wm * 32 + mi * 16 + r;
        #pragma unroll
        for (int ni = 0; ni < 8; ++ni) {
            int col = wn * 64 + ni * 8 + cc;
            if (gr0 < nrows) {
                __half2 v = __floats2half2_rn(c[mi][ni][0], c[mi][ni][1]);
                *(__half2*)(out + gr0 * D + col) = v;
            }
            if (gr0 + 8 < nrows) {
                __half2 v = __floats2half2_rn(c[mi][ni][2], c[mi][ni][3]);
                *(__half2*)(out + (gr0 + 8) * D + col) = v;
            }
        }
    }
}

// ---------------- SpMM + bias + relu: one warp/row, fp16 in/out, ILP=4 ------
__global__ void k_spmm(const __half* __restrict__ h, const float* __restrict__ bias,
                       __half* __restrict__ out, int nrows) {
    int w = (blockIdx.x * blockDim.x + threadIdx.x) >> 5;
    int lane = threadIdx.x & 31;
    if (w >= nrows) return;
    int p0 = g_rowptr[w], p1 = g_rowptr[w + 1];
    float4 acc = make_float4(0.f, 0.f, 0.f, 0.f);
    int p = p0;
    for (; p + 4 <= p1; p += 4) {
        int   c0 = g_col[p],     c1 = g_col[p + 1], c2 = g_col[p + 2], c3 = g_col[p + 3];
        float v0 = g_val[p],     v1 = g_val[p + 1], v2 = g_val[p + 2], v3 = g_val[p + 3];
        uint2 r0 = *(const uint2*)(h + c0 * D + lane * 4);
        uint2 r1 = *(const uint2*)(h + c1 * D + lane * 4);
        uint2 r2 = *(const uint2*)(h + c2 * D + lane * 4);
        uint2 r3 = *(const uint2*)(h + c3 * D + lane * 4);
        float2 a0 = __half22float2(*reinterpret_cast<__half2*>(&r0.x));
        float2 b0 = __half22float2(*reinterpret_cast<__half2*>(&r0.y));
        float2 a1 = __half22float2(*reinterpret_cast<__half2*>(&r1.x));
        float2 b1 = __half22float2(*reinterpret_cast<__half2*>(&r1.y));
        float2 a2 = __half22float2(*reinterpret_cast<__half2*>(&r2.x));
        float2 b2 = __half22float2(*reinterpret_cast<__half2*>(&r2.y));
        float2 a3 = __half22float2(*reinterpret_cast<__half2*>(&r3.x));
        float2 b3 = __half22float2(*reinterpret_cast<__half2*>(&r3.y));
        acc.x = fmaf(v0, a0.x, fmaf(v1, a1.x, fmaf(v2, a2.x, fmaf(v3, a3.x, acc.x))));
        acc.y = fmaf(v0, a0.y, fmaf(v1, a1.y, fmaf(v2, a2.y, fmaf(v3, a3.y, acc.y))));
        acc.z = fmaf(v0, b0.x, fmaf(v1, b1.x, fmaf(v2, b2.x, fmaf(v3, b3.x, acc.z))));
        acc.w = fmaf(v0, b0.y, fmaf(v1, b1.y, fmaf(v2, b2.y, fmaf(v3, b3.y, acc.w))));
    }
    for (; p < p1; ++p) {
        int cI = g_col[p]; float vI = g_val[p];
        uint2 rI = *(const uint2*)(h + cI * D + lane * 4);
        float2 fa = __half22float2(*reinterpret_cast<__half2*>(&rI.x));
        float2 fb = __half22float2(*reinterpret_cast<__half2*>(&rI.y));
        acc.x = fmaf(vI, fa.x, acc.x);
        acc.y = fmaf(vI, fa.y, acc.y);
        acc.z = fmaf(vI, fb.x, acc.z);
        acc.w = fmaf(vI, fb.y, acc.w);
    }
    float4 b = *(const float4*)(bias + lane * 4);
    acc.x = fmaxf(acc.x + b.x, 0.f);
    acc.y = fmaxf(acc.y + b.y, 0.f);
    acc.z = fmaxf(acc.z + b.z, 0.f);
    acc.w = fmaxf(acc.w + b.w, 0.f);
    __half2 o0 = __floats2half2_rn(acc.x, acc.y);
    __half2 o1 = __floats2half2_rn(acc.z, acc.w);
    uint2 ov;
    ov.x = *reinterpret_cast<uint32_t*>(&o0);
    ov.y = *reinterpret_cast<uint32_t*>(&o1);
    *(uint2*)(out + w * D + lane * 4) = ov;
}

// ---------------- pool: batch_vec sorted -> contiguous ranges ----------------
__global__ void k_pool(const __half* __restrict__ a, const int* __restrict__ batch,
                       float* __restrict__ out, int n) {
    int g = blockIdx.x, c = threadIdx.x;
    __shared__ int bounds[2];
    if (c < 2) {
        int target = g + c;
        int lo = 0, hi = n;
        while (lo < hi) {
            int mid = (lo + hi) >> 1;
            if (batch[mid] < target) lo = mid + 1; else hi = mid;
        }
        bounds[c] = lo;
    }
    __syncthreads();
    float sum = 0.f;
    for (int r = bounds[0]; r < bounds[1]; ++r) sum += __half2float(a[r * D + c]);
    out[g * D + c] = sum;
}

// ---------------- launch ----------------
extern "C" void kernel_launch(void* const* d_in, const int* in_sizes, int n_in,
                              void* d_out, int out_size) {
    const float* x  = (const float*)d_in[0];
    const float* W1 = (const float*)d_in[1];
    const float* b1 = (const float*)d_in[2];
    const float* W2 = (const float*)d_in[3];
    const float* b2 = (const float*)d_in[4];
    const float* W3 = (const float*)d_in[5];
    const float* b3 = (const float*)d_in[6];
    const int* ei    = (const int*)d_in[7];
    const int* batch = (const int*)d_in[8];
    float* out = (float*)d_out;

    int N = in_sizes[0] / D;
    int E = in_sizes[7] / 2;
    int G = out_size / D;

    __half *xbuf, *hbuf, *abuf;
    cudaGetSymbolAddress((void**)&xbuf, g_x16);
    cudaGetSymbolAddress((void**)&hbuf, g_h16);
    cudaGetSymbolAddress((void**)&abuf, g_a16);

    int smem = 2 * 128 * APITCH * (int)sizeof(__half);  // 69632 B
    cudaFuncSetAttribute(k_gemm_mma, cudaFuncAttributeMaxDynamicSharedMemorySize, smem);

    int nb = (N + 255) / 256;
    int eb = (E + 255) / 256;
    int sbk = (N + SCAN_B - 1) / SCAN_B;

    k_zero<<<nb, 256>>>(N);
    k_count<<<eb, 256>>>(ei + E, E);
    k_scanA<<<sbk, SCAN_B>>>(N);
    k_scanB<<<1, 128>>>(sbk, N);
    k_scanC<<<sbk, SCAN_B>>>(N);
    k_fill_edges<<<eb, 256>>>(ei, ei + E, E);

    int n4 = N * D / 4;
    k_cvt<<<(n4 + 255) / 256, 256>>>(x, xbuf, n4);

    int gb = (N + 127) / 128;
    int sb = (N * 32 + 255) / 256;

    k_gemm_mma<<<gb, 256, smem>>>(xbuf, W1, hbuf, N);
    k_spmm<<<sb, 256>>>(hbuf, b1, abuf, N);
    k_gemm_mma<<<gb, 256, smem>>>(abuf, W2, hbuf, N);
    k_spmm<<<sb, 256>>>(hbuf, b2, abuf, N);
    k_gemm_mma<<<gb, 256, smem>>>(abuf, W3, hbuf, N);
    k_spmm<<<sb, 256>>>(hbuf, b3, abuf, N);

    k_pool<<<G, 128>>>(abuf, batch, out, N);
}